// round 6
// baseline (speedup 1.0000x reference)
// Round 5 resubmission — identical oc-thirds kernel; previous bench run died to
// container infra ("GB300 container failed twice"), no measurement was taken.
#include <cuda_runtime.h>
#include <math.h>

#define BB   64
#define TT   32
#define HID  3
#define G    64
#define GG   4096
#define NOC  12
#define EPSV 1e-5f
#define FK   37
#define OUTW 28

typedef unsigned long long u64;

// ---------------- packed f32x2 helpers (Blackwell FFMA2 path) ----------------
__device__ __forceinline__ u64 pack2(float x) {
    u64 d; unsigned u = __float_as_uint(x);
    asm("mov.b64 %0, {%1, %1};" : "=l"(d) : "r"(u));
    return d;
}
__device__ __forceinline__ u64 packlh(float lo, float hi) {
    u64 d; unsigned a = __float_as_uint(lo), b = __float_as_uint(hi);
    asm("mov.b64 %0, {%1, %2};" : "=l"(d) : "r"(a), "r"(b));
    return d;
}
__device__ __forceinline__ void ffma2(u64 &acc, u64 a, u64 b) {
    asm("fma.rn.f32x2 %0, %1, %2, %0;" : "+l"(acc) : "l"(a), "l"(b));
}
__device__ __forceinline__ void unpack2(u64 d, float &lo, float &hi) {
    unsigned a, b;
    asm("mov.b64 {%0, %1}, %2;" : "=r"(a), "=r"(b) : "l"(d));
    lo = __uint_as_float(a); hi = __uint_as_float(b);
}

// fast sigmoid / tanh (~1e-6 rel err)
__device__ __forceinline__ float fsig(float x) {
    float t, r;
    asm("mul.f32 %0, %1, 0fBFB8AA3B;" : "=f"(t) : "f"(x));
    asm("ex2.approx.f32 %0, %0;" : "+f"(t));
    asm("add.f32 %0, %0, 0f3F800000;" : "+f"(t));
    asm("rcp.approx.f32 %0, %1;" : "=f"(r) : "f"(t));
    return r;
}
__device__ __forceinline__ float ftanh(float x) {
    return fmaf(2.f, fsig(2.f * x), -1.f);
}

// ---------------- static device scratch ----------------
__device__ float g_h[BB*HID*GG];
__device__ float g_c[BB*HID*GG];
__device__ float g_z[BB*NOC*GG];
__device__ float g_part[BB*8*3*4];   // [b][tile][third][idx*2+which]

__global__ void k_init() {
    int i = blockIdx.x * blockDim.x + threadIdx.x;
    if (i < BB*HID*GG) { g_h[i] = 0.f; g_c[i] = 0.f; }
}

// ---------------- per-step conv, split into oc-THIRDS for occupancy ------------
// grid: BB*24 blocks = (b, tile 0..7, third 0..2); 16x32 tile, 128 thr, 4 px
// third covers oc [third*4, third*4+4): weights are one aligned LDS.128 per tap
__global__ __launch_bounds__(128, 8) void k_conv(const float* __restrict__ x,
                                                 const float* __restrict__ Wg,
                                                 const float* __restrict__ bg,
                                                 int t)
{
    __shared__ __align__(16) float ts[4*26*44];     // input tile, row stride 44 (18.3KB)
    __shared__ __align__(16) float wsm[4*121*4];    // weights [ic][ky][kx][ocl(4)] (7.7KB)
    __shared__ float sred[4][4];

    const int tid   = threadIdx.x;
    const int b     = blockIdx.x / 24;
    const int rem   = blockIdx.x - b*24;
    const int tile  = rem / 3;                    // 0..7: 4 row-tiles x 2 col-tiles
    const int third = rem - tile*3;               // 0..2
    const int ty0   = (tile >> 1) << 4;           // 0,16,32,48
    const int tx0   = (tile & 1) << 5;            // 0,32

    // weights: wsm[(ic*121+kk)*4 + ocl] = Wg[((third*4+ocl)*4+ic)*121+kk]
    for (int i = tid; i < 4*121*4; i += 128) {
        int ocl = i & 3;
        int k   = i >> 2;
        int ic  = k / 121;
        int kk  = k - ic*121;
        wsm[i] = Wg[((third*4 + ocl)*4 + ic)*121 + kk];
    }
    const float* xb = x + (size_t)(b*TT + t) * GG;
    for (int i = tid; i < 4*26*42; i += 128) {
        int ic  = i / 1092;
        int rm  = i - ic*1092;
        int r   = rm / 42;
        int cc  = rm - r*42;
        int gy = ty0 - 5 + r;
        int gx = tx0 - 5 + cc;
        float v = 0.f;
        if (gy >= 0 && gy < G && gx >= 0 && gx < G) {
            v = (ic == 0) ? xb[gy*G + gx]
                          : g_h[(b*HID + ic - 1)*GG + gy*G + gx];
        }
        ts[(ic*26 + r)*44 + cc] = v;
    }
    __syncthreads();

    const int ty  = tid >> 3;           // 0..15
    const int tx4 = (tid & 7) << 2;     // 0,4,..,28

    // acc[p][j]: pixel p, oc pair (third*4+2j, third*4+2j+1); init with bias
    u64 acc[4][2];
    #pragma unroll
    for (int j = 0; j < 2; j++) {
        u64 bp = packlh(bg[third*4 + 2*j], bg[third*4 + 2*j + 1]);
        #pragma unroll
        for (int p = 0; p < 4; p++) acc[p][j] = bp;
    }

    #pragma unroll 1
    for (int ic = 0; ic < 4; ic++) {
        #pragma unroll 1
        for (int ky = 0; ky < 11; ky++) {
            const float* rowp = &ts[(ic*26 + ty + ky)*44 + tx4];
            u64 winp[14];
            {
                float4 a = ((const float4*)rowp)[0];
                float4 c = ((const float4*)rowp)[1];
                float4 e = ((const float4*)rowp)[2];
                float2 f = *(const float2*)(rowp + 12);
                winp[0]=pack2(a.x);  winp[1]=pack2(a.y);  winp[2]=pack2(a.z);  winp[3]=pack2(a.w);
                winp[4]=pack2(c.x);  winp[5]=pack2(c.y);  winp[6]=pack2(c.z);  winp[7]=pack2(c.w);
                winp[8]=pack2(e.x);  winp[9]=pack2(e.y);  winp[10]=pack2(e.z); winp[11]=pack2(e.w);
                winp[12]=pack2(f.x); winp[13]=pack2(f.y);
            }
            const ulonglong2* wp = (const ulonglong2*)&wsm[(ic*121 + ky*11)*4];
            #pragma unroll
            for (int kx = 0; kx < 11; kx++) {
                ulonglong2 w = wp[kx];            // one LDS.128: oc pair0, pair1
                #pragma unroll
                for (int p = 0; p < 4; p++) {
                    ffma2(acc[p][0], winp[kx+p], w.x);
                    ffma2(acc[p][1], winp[kx+p], w.y);
                }
            }
        }
    }

    // unpack, store z, LN partial sums (this third spans exactly 2 gates)
    const int gy = ty0 + ty;
    const int gx = tx0 + tx4;
    const int gA = (third*4) / 3;        // first gate this third touches
    float s[2]  = {0.f, 0.f};
    float ss[2] = {0.f, 0.f};
    #pragma unroll
    for (int j = 0; j < 2; j++) {
        float z0[4], z1[4];
        #pragma unroll
        for (int p = 0; p < 4; p++) unpack2(acc[p][j], z0[p], z1[p]);
        int oc0 = third*4 + 2*j;
        int oc1 = oc0 + 1;
        int i0  = oc0/3 - gA;            // 0 or 1
        int i1  = oc1/3 - gA;
        float4 v0, v1;
        v0.x=z0[0]; v0.y=z0[1]; v0.z=z0[2]; v0.w=z0[3];
        v1.x=z1[0]; v1.y=z1[1]; v1.z=z1[2]; v1.w=z1[3];
        #pragma unroll
        for (int p = 0; p < 4; p++) {
            s[i0]  += z0[p];  ss[i0] += z0[p]*z0[p];
            s[i1]  += z1[p];  ss[i1] += z1[p]*z1[p];
        }
        *(float4*)&g_z[(size_t)(b*12 + oc0)*GG + gy*G + gx] = v0;
        *(float4*)&g_z[(size_t)(b*12 + oc1)*GG + gy*G + gx] = v1;
    }

    const int lane = tid & 31;
    const int wrp  = tid >> 5;
    #pragma unroll
    for (int g = 0; g < 2; g++) {
        #pragma unroll
        for (int off = 16; off > 0; off >>= 1) {
            s[g]  += __shfl_down_sync(0xFFFFFFFFu, s[g],  off);
            ss[g] += __shfl_down_sync(0xFFFFFFFFu, ss[g], off);
        }
    }
    if (lane == 0) {
        sred[wrp][0] = s[0];  sred[wrp][1] = ss[0];
        sred[wrp][2] = s[1];  sred[wrp][3] = ss[1];
    }
    __syncthreads();
    if (tid < 4) {
        float v = sred[0][tid] + sred[1][tid] + sred[2][tid] + sred[3][tid];
        g_part[((b*8 + tile)*3 + third)*4 + tid] = v;
    }
}

// ---------------- pointwise gate update, float4-vectorized ----------------------
// grid: BB*12 blocks; block covers 1024 consecutive r*4 lanes of one batch b
__global__ __launch_bounds__(256) void k_gates(const float* __restrict__ wci,
                                               const float* __restrict__ wcf,
                                               const float* __restrict__ wco,
                                               const float* __restrict__ lnw,
                                               const float* __restrict__ lnb)
{
    __shared__ float st[8];
    const int b = blockIdx.x / 12;
    const int r = ((blockIdx.x % 12) * 256 + threadIdx.x) * 4;

    if (threadIdx.x < 4) {
        int gt = threadIdx.x;
        float s = 0.f, ssum = 0.f;
        // gate gt gathers from (third=gt-1, idx=1) and (third=gt, idx=0)
        #pragma unroll
        for (int tl = 0; tl < 8; tl++) {
            int base = (b*8 + tl)*3;
            if (gt > 0) {
                s    += g_part[(base + gt - 1)*4 + 2];
                ssum += g_part[(base + gt - 1)*4 + 3];
            }
            if (gt < 3) {
                s    += g_part[(base + gt)*4 + 0];
                ssum += g_part[(base + gt)*4 + 1];
            }
        }
        const float inv = 1.f / 12288.f;
        float mu  = s * inv;
        float var = fmaxf(ssum * inv - mu*mu, 0.f);
        st[gt*2 + 0] = mu;
        st[gt*2 + 1] = rsqrtf(var + EPSV);
    }
    __syncthreads();

    const size_t zb = (size_t)b * 12 * GG;
    float4 zi = *(const float4*)&g_z[zb + 0*12288 + r];
    float4 zf = *(const float4*)&g_z[zb + 1*12288 + r];
    float4 zg = *(const float4*)&g_z[zb + 2*12288 + r];
    float4 zo = *(const float4*)&g_z[zb + 3*12288 + r];
    float4 wi = *(const float4*)&lnw[0*12288 + r];
    float4 bi = *(const float4*)&lnb[0*12288 + r];
    float4 wf = *(const float4*)&lnw[1*12288 + r];
    float4 bf = *(const float4*)&lnb[1*12288 + r];
    float4 wg = *(const float4*)&lnw[2*12288 + r];
    float4 bgv= *(const float4*)&lnb[2*12288 + r];
    float4 wo = *(const float4*)&lnw[3*12288 + r];
    float4 bo = *(const float4*)&lnb[3*12288 + r];
    float4 ci = *(const float4*)&wci[r];
    float4 cf = *(const float4*)&wcf[r];
    float4 co = *(const float4*)&wco[r];
    float4 c4 = *(const float4*)&g_c[b*12288 + r];

    float4 cn4, hn4;
    #pragma unroll
    for (int k = 0; k < 4; k++) {
        float vzi = ((const float*)&zi)[k], vzf = ((const float*)&zf)[k];
        float vzg = ((const float*)&zg)[k], vzo = ((const float*)&zo)[k];
        vzi = (vzi - st[0]) * st[1] * ((const float*)&wi)[k] + ((const float*)&bi)[k];
        vzf = (vzf - st[2]) * st[3] * ((const float*)&wf)[k] + ((const float*)&bf)[k];
        vzg = (vzg - st[4]) * st[5] * ((const float*)&wg)[k] + ((const float*)&bgv)[k];
        vzo = (vzo - st[6]) * st[7] * ((const float*)&wo)[k] + ((const float*)&bo)[k];
        float c  = ((const float*)&c4)[k];
        float ig = fsig(vzi + ((const float*)&ci)[k]*c);
        float fg = fsig(vzf + ((const float*)&cf)[k]*c);
        float cn = fg*c + ig*ftanh(vzg);
        float og = fsig(vzo + ((const float*)&co)[k]*cn);
        ((float*)&cn4)[k] = cn;
        ((float*)&hn4)[k] = og * ftanh(cn);
    }
    *(float4*)&g_c[b*12288 + r] = cn4;
    *(float4*)&g_h[b*12288 + r] = hn4;
}

// ---------------- final 37x37 valid conv ----------------
__global__ __launch_bounds__(128) void k_final(const float* __restrict__ cw,
                                               const float* __restrict__ cb,
                                               float* __restrict__ out)
{
    __shared__ float hs[40*64];
    __shared__ float ws[FK*FK];
    const int b   = blockIdx.x / 7;
    const int seg = blockIdx.x % 7;
    const int oy0 = seg * 4;
    const int tid = threadIdx.x;
    const int ly  = tid / 28;
    const int ox  = tid % 28;

    float acc = 0.f;
    for (int hc = 0; hc < HID; hc++) {
        __syncthreads();
        for (int i = tid; i < 40*64; i += 128) {
            int r = i / 64;
            hs[i] = g_h[(size_t)(b*HID + hc)*GG + (oy0 + r)*G + (i - r*64)];
        }
        for (int i = tid; i < FK*FK; i += 128) ws[i] = cw[hc*FK*FK + i];
        __syncthreads();
        if (tid < 112) {
            #pragma unroll 1
            for (int ky = 0; ky < FK; ky++) {
                const float* hr = &hs[(ly + ky)*64 + ox];
                const float* wr = &ws[ky*FK];
                float a = 0.f;
                #pragma unroll
                for (int kx = 0; kx < FK; kx++) a = fmaf(hr[kx], wr[kx], a);
                acc += a;
            }
        }
    }
    if (tid < 112) {
        int oy = oy0 + ly;
        out[b*OUTW*OUTW + oy*OUTW + ox] = acc + cb[0];
    }
}

// ---------------- launch ----------------
extern "C" void kernel_launch(void* const* d_in, const int* in_sizes, int n_in,
                              void* d_out, int out_size)
{
    const float* x   = (const float*)d_in[0];
    const float* Wg  = (const float*)d_in[1];
    const float* bg  = (const float*)d_in[2];
    const float* wci = (const float*)d_in[3];
    const float* wcf = (const float*)d_in[4];
    const float* wco = (const float*)d_in[5];
    const float* lnw = (const float*)d_in[6];
    const float* lnb = (const float*)d_in[7];
    const float* cw  = (const float*)d_in[8];
    const float* cb  = (const float*)d_in[9];
    float* out = (float*)d_out;

    k_init<<<(BB*HID*GG + 255)/256, 256>>>();
    for (int t = 0; t < TT; t++) {
        k_conv<<<BB*24, 128>>>(x, Wg, bg, t);
        k_gates<<<BB*12, 256>>>(wci, wcf, wco, lnw, lnb);
    }
    k_final<<<BB*7, 128>>>(cw, cb, out);
}

// round 7
// speedup vs baseline: 1.1361x; 1.1361x over previous
// Round 7: round-4 halves structure (best: 2312us) + weights staged into
// __constant__ memory (uniform LDCU path) instead of per-block smem.
#include <cuda_runtime.h>
#include <math.h>

#define BB   64
#define TT   32
#define HID  3
#define G    64
#define GG   4096
#define NOC  12
#define EPSV 1e-5f
#define FK   37
#define OUTW 28

typedef unsigned long long u64;

// ---------------- packed f32x2 helpers (Blackwell FFMA2 path) ----------------
__device__ __forceinline__ u64 pack2(float x) {
    u64 d; unsigned u = __float_as_uint(x);
    asm("mov.b64 %0, {%1, %1};" : "=l"(d) : "r"(u));
    return d;
}
__device__ __forceinline__ u64 packlh(float lo, float hi) {
    u64 d; unsigned a = __float_as_uint(lo), b = __float_as_uint(hi);
    asm("mov.b64 %0, {%1, %2};" : "=l"(d) : "r"(a), "r"(b));
    return d;
}
__device__ __forceinline__ void ffma2(u64 &acc, u64 a, u64 b) {
    asm("fma.rn.f32x2 %0, %1, %2, %0;" : "+l"(acc) : "l"(a), "l"(b));
}
__device__ __forceinline__ void unpack2(u64 d, float &lo, float &hi) {
    unsigned a, b;
    asm("mov.b64 {%0, %1}, %2;" : "=r"(a), "=r"(b) : "l"(d));
    lo = __uint_as_float(a); hi = __uint_as_float(b);
}

// fast sigmoid / tanh (~1e-6 rel err)
__device__ __forceinline__ float fsig(float x) {
    float t, r;
    asm("mul.f32 %0, %1, 0fBFB8AA3B;" : "=f"(t) : "f"(x));
    asm("ex2.approx.f32 %0, %0;" : "+f"(t));
    asm("add.f32 %0, %0, 0f3F800000;" : "+f"(t));
    asm("rcp.approx.f32 %0, %1;" : "=f"(r) : "f"(t));
    return r;
}
__device__ __forceinline__ float ftanh(float x) {
    return fmaf(2.f, fsig(2.f * x), -1.f);
}

// ---------------- static device scratch ----------------
__device__ float g_h[BB*HID*GG];
__device__ float g_c[BB*HID*GG];
__device__ float g_z[BB*NOC*GG];
__device__ float g_part[BB*8*2*4];   // [b][tile][half][gate_local*2+which]
__device__ float g_wtmp[2*4*121*6];  // rearranged weights staging buffer

// constant-memory weights: c_W[((half*4 + ic)*121 + kk)*6 + ocl]
__constant__ float c_W[2*4*121*6];   // 23.2 KB

__global__ void k_init() {
    int i = blockIdx.x * blockDim.x + threadIdx.x;
    if (i < BB*HID*GG) { g_h[i] = 0.f; g_c[i] = 0.f; }
}

// rearrange Wg [oc][ic][11][11] -> g_wtmp [half][ic][kk][ocl]
__global__ void k_prep(const float* __restrict__ Wg) {
    int i = blockIdx.x * blockDim.x + threadIdx.x;
    if (i >= 2*4*121*6) return;
    int ocl  = i % 6;
    int rest = i / 6;
    int kk   = rest % 121;
    int hic  = rest / 121;
    int ic   = hic & 3;
    int half = hic >> 2;
    g_wtmp[i] = Wg[((half*6 + ocl)*4 + ic)*121 + kk];
}

// ---------------- per-step conv, oc-halves, weights from __constant__ -----------
// grid: BB*16 blocks = (b, tile 0..7, half 0..1); 16x32 output tile, 128 thr, 4 px
__global__ __launch_bounds__(128, 7) void k_conv(const float* __restrict__ x,
                                                 const float* __restrict__ bg,
                                                 int t)
{
    __shared__ __align__(16) float ts[4*26*44];     // input tile, row stride 44 (18.3KB)
    __shared__ float sred[4][4];

    const int tid  = threadIdx.x;
    const int b    = blockIdx.x >> 4;
    const int rem  = blockIdx.x & 15;
    const int tile = rem >> 1;                    // 0..7: 4 row-tiles x 2 col-tiles
    const int half = rem & 1;
    const int ty0  = (tile >> 1) << 4;            // 0,16,32,48
    const int tx0  = (tile & 1) << 5;             // 0,32

    const float* xb = x + (size_t)(b*TT + t) * GG;
    for (int i = tid; i < 4*26*42; i += 128) {
        int ic  = i / 1092;
        int rm  = i - ic*1092;
        int r   = rm / 42;
        int cc  = rm - r*42;
        int gy = ty0 - 5 + r;
        int gx = tx0 - 5 + cc;
        float v = 0.f;
        if (gy >= 0 && gy < G && gx >= 0 && gx < G) {
            v = (ic == 0) ? xb[gy*G + gx]
                          : g_h[(b*HID + ic - 1)*GG + gy*G + gx];
        }
        ts[(ic*26 + r)*44 + cc] = v;
    }
    __syncthreads();

    const int ty  = tid >> 3;           // 0..15
    const int tx4 = (tid & 7) << 2;     // 0,4,..,28

    // acc[p][j]: pixel p, oc pair (half*6+2j, half*6+2j+1); init with bias
    u64 acc[4][3];
    #pragma unroll
    for (int j = 0; j < 3; j++) {
        u64 bp = packlh(bg[half*6 + 2*j], bg[half*6 + 2*j + 1]);
        #pragma unroll
        for (int p = 0; p < 4; p++) acc[p][j] = bp;
    }

    #pragma unroll 1
    for (int ic = 0; ic < 4; ic++) {
        #pragma unroll 1
        for (int ky = 0; ky < 11; ky++) {
            const float* rowp = &ts[(ic*26 + ty + ky)*44 + tx4];
            u64 winp[14];
            {
                float4 a = ((const float4*)rowp)[0];
                float4 c = ((const float4*)rowp)[1];
                float4 e = ((const float4*)rowp)[2];
                float2 f = *(const float2*)(rowp + 12);
                winp[0]=pack2(a.x);  winp[1]=pack2(a.y);  winp[2]=pack2(a.z);  winp[3]=pack2(a.w);
                winp[4]=pack2(c.x);  winp[5]=pack2(c.y);  winp[6]=pack2(c.z);  winp[7]=pack2(c.w);
                winp[8]=pack2(e.x);  winp[9]=pack2(e.y);  winp[10]=pack2(e.z); winp[11]=pack2(e.w);
                winp[12]=pack2(f.x); winp[13]=pack2(f.y);
            }
            // weights from constant memory: uniform address, compile-time offsets
            const float* wrow = &c_W[((half*4 + ic)*121 + ky*11)*6];
            #pragma unroll
            for (int kx = 0; kx < 11; kx++) {
                u64 w0 = *(const u64*)(wrow + kx*6 + 0);
                u64 w1 = *(const u64*)(wrow + kx*6 + 2);
                u64 w2 = *(const u64*)(wrow + kx*6 + 4);
                #pragma unroll
                for (int p = 0; p < 4; p++) {
                    ffma2(acc[p][0], winp[kx+p], w0);
                    ffma2(acc[p][1], winp[kx+p], w1);
                    ffma2(acc[p][2], winp[kx+p], w2);
                }
            }
        }
    }

    // unpack, store z, LN partial sums (this half covers 2 gates)
    const int gy = ty0 + ty;
    const int gx = tx0 + tx4;
    float s[2]  = {0.f, 0.f};
    float ss[2] = {0.f, 0.f};
    #pragma unroll
    for (int j = 0; j < 3; j++) {
        float z0[4], z1[4];
        #pragma unroll
        for (int p = 0; p < 4; p++) unpack2(acc[p][j], z0[p], z1[p]);
        int gl0 = (2*j)   / 3;   // local gate of oc half*6+2j
        int gl1 = (2*j+1) / 3;
        float4 v0, v1;
        v0.x=z0[0]; v0.y=z0[1]; v0.z=z0[2]; v0.w=z0[3];
        v1.x=z1[0]; v1.y=z1[1]; v1.z=z1[2]; v1.w=z1[3];
        #pragma unroll
        for (int p = 0; p < 4; p++) {
            s[gl0]  += z0[p];  ss[gl0] += z0[p]*z0[p];
            s[gl1]  += z1[p];  ss[gl1] += z1[p]*z1[p];
        }
        *(float4*)&g_z[(size_t)(b*12 + half*6 + 2*j    )*GG + gy*G + gx] = v0;
        *(float4*)&g_z[(size_t)(b*12 + half*6 + 2*j + 1)*GG + gy*G + gx] = v1;
    }

    const int lane = tid & 31;
    const int wrp  = tid >> 5;
    #pragma unroll
    for (int g = 0; g < 2; g++) {
        #pragma unroll
        for (int off = 16; off > 0; off >>= 1) {
            s[g]  += __shfl_down_sync(0xFFFFFFFFu, s[g],  off);
            ss[g] += __shfl_down_sync(0xFFFFFFFFu, ss[g], off);
        }
    }
    if (lane == 0) {
        sred[wrp][0] = s[0];  sred[wrp][1] = ss[0];
        sred[wrp][2] = s[1];  sred[wrp][3] = ss[1];
    }
    __syncthreads();
    if (tid < 4) {
        float v = sred[0][tid] + sred[1][tid] + sred[2][tid] + sred[3][tid];
        g_part[((b*8 + tile)*2 + half)*4 + tid] = v;
    }
}

// ---------------- pointwise gate update, float4-vectorized ----------------------
__global__ __launch_bounds__(256) void k_gates(const float* __restrict__ wci,
                                               const float* __restrict__ wcf,
                                               const float* __restrict__ wco,
                                               const float* __restrict__ lnw,
                                               const float* __restrict__ lnb)
{
    __shared__ float st[8];
    const int b   = blockIdx.x / 12;
    const int r   = ((blockIdx.x % 12) * 256 + threadIdx.x) * 4;

    if (threadIdx.x < 4) {
        int gt   = threadIdx.x;
        int half = gt >> 1;
        int gl   = gt & 1;
        float s = 0.f, ssum = 0.f;
        #pragma unroll
        for (int tl = 0; tl < 8; tl++) {
            s    += g_part[((b*8 + tl)*2 + half)*4 + gl*2 + 0];
            ssum += g_part[((b*8 + tl)*2 + half)*4 + gl*2 + 1];
        }
        const float inv = 1.f / 12288.f;
        float mu  = s * inv;
        float var = fmaxf(ssum * inv - mu*mu, 0.f);
        st[gt*2 + 0] = mu;
        st[gt*2 + 1] = rsqrtf(var + EPSV);
    }
    __syncthreads();

    const size_t zb = (size_t)b * 12 * GG;
    float4 zi = *(const float4*)&g_z[zb + 0*12288 + r];
    float4 zf = *(const float4*)&g_z[zb + 1*12288 + r];
    float4 zg = *(const float4*)&g_z[zb + 2*12288 + r];
    float4 zo = *(const float4*)&g_z[zb + 3*12288 + r];
    float4 wi = *(const float4*)&lnw[0*12288 + r];
    float4 bi = *(const float4*)&lnb[0*12288 + r];
    float4 wf = *(const float4*)&lnw[1*12288 + r];
    float4 bf = *(const float4*)&lnb[1*12288 + r];
    float4 wg = *(const float4*)&lnw[2*12288 + r];
    float4 bgv= *(const float4*)&lnb[2*12288 + r];
    float4 wo = *(const float4*)&lnw[3*12288 + r];
    float4 bo = *(const float4*)&lnb[3*12288 + r];
    float4 ci = *(const float4*)&wci[r];
    float4 cf = *(const float4*)&wcf[r];
    float4 co = *(const float4*)&wco[r];
    float4 c4 = *(const float4*)&g_c[b*12288 + r];

    float4 cn4, hn4;
    #pragma unroll
    for (int k = 0; k < 4; k++) {
        float vzi = ((const float*)&zi)[k], vzf = ((const float*)&zf)[k];
        float vzg = ((const float*)&zg)[k], vzo = ((const float*)&zo)[k];
        vzi = (vzi - st[0]) * st[1] * ((const float*)&wi)[k] + ((const float*)&bi)[k];
        vzf = (vzf - st[2]) * st[3] * ((const float*)&wf)[k] + ((const float*)&bf)[k];
        vzg = (vzg - st[4]) * st[5] * ((const float*)&wg)[k] + ((const float*)&bgv)[k];
        vzo = (vzo - st[6]) * st[7] * ((const float*)&wo)[k] + ((const float*)&bo)[k];
        float c  = ((const float*)&c4)[k];
        float ig = fsig(vzi + ((const float*)&ci)[k]*c);
        float fg = fsig(vzf + ((const float*)&cf)[k]*c);
        float cn = fg*c + ig*ftanh(vzg);
        float og = fsig(vzo + ((const float*)&co)[k]*cn);
        ((float*)&cn4)[k] = cn;
        ((float*)&hn4)[k] = og * ftanh(cn);
    }
    *(float4*)&g_c[b*12288 + r] = cn4;
    *(float4*)&g_h[b*12288 + r] = hn4;
}

// ---------------- final 37x37 valid conv ----------------
__global__ __launch_bounds__(128) void k_final(const float* __restrict__ cw,
                                               const float* __restrict__ cb,
                                               float* __restrict__ out)
{
    __shared__ float hs[40*64];
    __shared__ float ws[FK*FK];
    const int b   = blockIdx.x / 7;
    const int seg = blockIdx.x % 7;
    const int oy0 = seg * 4;
    const int tid = threadIdx.x;
    const int ly  = tid / 28;
    const int ox  = tid % 28;

    float acc = 0.f;
    for (int hc = 0; hc < HID; hc++) {
        __syncthreads();
        for (int i = tid; i < 40*64; i += 128) {
            int r = i / 64;
            hs[i] = g_h[(size_t)(b*HID + hc)*GG + (oy0 + r)*G + (i - r*64)];
        }
        for (int i = tid; i < FK*FK; i += 128) ws[i] = cw[hc*FK*FK + i];
        __syncthreads();
        if (tid < 112) {
            #pragma unroll 1
            for (int ky = 0; ky < FK; ky++) {
                const float* hr = &hs[(ly + ky)*64 + ox];
                const float* wr = &ws[ky*FK];
                float a = 0.f;
                #pragma unroll
                for (int kx = 0; kx < FK; kx++) a = fmaf(hr[kx], wr[kx], a);
                acc += a;
            }
        }
    }
    if (tid < 112) {
        int oy = oy0 + ly;
        out[b*OUTW*OUTW + oy*OUTW + ox] = acc + cb[0];
    }
}

// ---------------- launch ----------------
extern "C" void kernel_launch(void* const* d_in, const int* in_sizes, int n_in,
                              void* d_out, int out_size)
{
    const float* x   = (const float*)d_in[0];
    const float* Wg  = (const float*)d_in[1];
    const float* bg  = (const float*)d_in[2];
    const float* wci = (const float*)d_in[3];
    const float* wcf = (const float*)d_in[4];
    const float* wco = (const float*)d_in[5];
    const float* lnw = (const float*)d_in[6];
    const float* lnb = (const float*)d_in[7];
    const float* cw  = (const float*)d_in[8];
    const float* cb  = (const float*)d_in[9];
    float* out = (float*)d_out;

    k_init<<<(BB*HID*GG + 255)/256, 256>>>();

    // stage rearranged weights into constant memory (graph-capturable: kernel +
    // async D2D memcpy; no allocation)
    k_prep<<<(2*4*121*6 + 255)/256, 256>>>(Wg);
    void* wtmp_addr = nullptr;
    cudaGetSymbolAddress(&wtmp_addr, g_wtmp);
    cudaMemcpyToSymbolAsync(c_W, wtmp_addr, sizeof(float)*2*4*121*6, 0,
                            cudaMemcpyDeviceToDevice, 0);

    for (int t = 0; t < TT; t++) {
        k_conv<<<BB*16, 128>>>(x, bg, t);
        k_gates<<<BB*12, 256>>>(wci, wcf, wco, lnw, lnb);
    }
    k_final<<<BB*7, 128>>>(cw, cb, out);
}

// round 8
// speedup vs baseline: 1.2275x; 1.0804x over previous
// Round 8: round-4 base (best 2312us, smem weights) + 2-phase ic tiling to cut
// conv smem 30->21KB enabling 8 blocks/SM, + k_gates load-before-stats.
#include <cuda_runtime.h>
#include <math.h>

#define BB   64
#define TT   32
#define HID  3
#define G    64
#define GG   4096
#define NOC  12
#define EPSV 1e-5f
#define FK   37
#define OUTW 28

typedef unsigned long long u64;

// ---------------- packed f32x2 helpers (Blackwell FFMA2 path) ----------------
__device__ __forceinline__ u64 pack2(float x) {
    u64 d; unsigned u = __float_as_uint(x);
    asm("mov.b64 %0, {%1, %1};" : "=l"(d) : "r"(u));
    return d;
}
__device__ __forceinline__ u64 packlh(float lo, float hi) {
    u64 d; unsigned a = __float_as_uint(lo), b = __float_as_uint(hi);
    asm("mov.b64 %0, {%1, %2};" : "=l"(d) : "r"(a), "r"(b));
    return d;
}
__device__ __forceinline__ void ffma2(u64 &acc, u64 a, u64 b) {
    asm("fma.rn.f32x2 %0, %1, %2, %0;" : "+l"(acc) : "l"(a), "l"(b));
}
__device__ __forceinline__ void unpack2(u64 d, float &lo, float &hi) {
    unsigned a, b;
    asm("mov.b64 {%0, %1}, %2;" : "=r"(a), "=r"(b) : "l"(d));
    lo = __uint_as_float(a); hi = __uint_as_float(b);
}

// fast sigmoid / tanh (~1e-6 rel err)
__device__ __forceinline__ float fsig(float x) {
    float t, r;
    asm("mul.f32 %0, %1, 0fBFB8AA3B;" : "=f"(t) : "f"(x));
    asm("ex2.approx.f32 %0, %0;" : "+f"(t));
    asm("add.f32 %0, %0, 0f3F800000;" : "+f"(t));
    asm("rcp.approx.f32 %0, %1;" : "=f"(r) : "f"(t));
    return r;
}
__device__ __forceinline__ float ftanh(float x) {
    return fmaf(2.f, fsig(2.f * x), -1.f);
}

// ---------------- static device scratch ----------------
__device__ float g_h[BB*HID*GG];
__device__ float g_c[BB*HID*GG];
__device__ float g_z[BB*NOC*GG];
__device__ float g_part[BB*8*2*4];   // [b][tile][half][gate_local*2+which]

__global__ void k_init() {
    int i = blockIdx.x * blockDim.x + threadIdx.x;
    if (i < BB*HID*GG) { g_h[i] = 0.f; g_c[i] = 0.f; }
}

// ---------------- per-step conv, oc-halves, 2-phase ic tiling -------------------
// grid: BB*16 blocks = (b, tile 0..7, half 0..1); 16x32 output tile, 128 thr, 4 px
// Phase icp=0 processes ic{0,1}, icp=1 processes ic{2,3}; tile buffer reused.
__global__ __launch_bounds__(128, 8) void k_conv(const float* __restrict__ x,
                                                 const float* __restrict__ Wg,
                                                 const float* __restrict__ bg,
                                                 int t)
{
    __shared__ __align__(16) float ts[2*26*44];     // 2-ic input tile (9.2KB)
    __shared__ __align__(16) float wsm[4*121*6];    // weights [ic][ky][kx][ocl] (11.6KB)
    __shared__ float sred[4][4];

    const int tid  = threadIdx.x;
    const int b    = blockIdx.x >> 4;
    const int rem  = blockIdx.x & 15;
    const int tile = rem >> 1;                    // 0..7: 4 row-tiles x 2 col-tiles
    const int half = rem & 1;
    const int ty0  = (tile >> 1) << 4;            // 0,16,32,48
    const int tx0  = (tile & 1) << 5;             // 0,32

    // weights for this half: wsm[(ic*121+kk)*6 + ocl] = Wg[((half*6+ocl)*4+ic)*121+kk]
    for (int i = tid; i < 4*121*6; i += 128) {
        int ocl = i % 6;
        int k   = i / 6;
        int ic  = k / 121;
        int kk  = k - ic*121;
        wsm[i] = Wg[((half*6 + ocl)*4 + ic)*121 + kk];
    }

    const float* xb = x + (size_t)(b*TT + t) * GG;
    const int ty  = tid >> 3;           // 0..15
    const int tx4 = (tid & 7) << 2;     // 0,4,..,28

    // acc[p][j]: pixel p, oc pair (half*6+2j, half*6+2j+1); init with bias
    u64 acc[4][3];
    #pragma unroll
    for (int j = 0; j < 3; j++) {
        u64 bp = packlh(bg[half*6 + 2*j], bg[half*6 + 2*j + 1]);
        #pragma unroll
        for (int p = 0; p < 4; p++) acc[p][j] = bp;
    }

    #pragma unroll 1
    for (int icp = 0; icp < 2; icp++) {
        if (icp) __syncthreads();   // protect ts before overwrite (phase 1)
        // load 2-ic tile for ic = 2*icp, 2*icp+1
        for (int i = tid; i < 2*26*42; i += 128) {
            int icl = i / 1092;
            int rm  = i - icl*1092;
            int r   = rm / 42;
            int cc  = rm - r*42;
            int ic  = icp*2 + icl;
            int gy = ty0 - 5 + r;
            int gx = tx0 - 5 + cc;
            float v = 0.f;
            if (gy >= 0 && gy < G && gx >= 0 && gx < G) {
                v = (ic == 0) ? xb[gy*G + gx]
                              : g_h[(b*HID + ic - 1)*GG + gy*G + gx];
            }
            ts[(icl*26 + r)*44 + cc] = v;
        }
        __syncthreads();

        #pragma unroll 1
        for (int icl = 0; icl < 2; icl++) {
            const int ic = icp*2 + icl;
            #pragma unroll 1
            for (int ky = 0; ky < 11; ky++) {
                const float* rowp = &ts[(icl*26 + ty + ky)*44 + tx4];
                const u64*   wp   = (const u64*)&wsm[(ic*121 + ky*11)*6];

                // --- section 1: kx = 0..5, inputs [0..8] ---
                {
                    u64 winp[9];
                    {
                        float4 a = ((const float4*)rowp)[0];
                        float4 c = ((const float4*)rowp)[1];
                        float  e = rowp[8];
                        winp[0]=pack2(a.x); winp[1]=pack2(a.y); winp[2]=pack2(a.z); winp[3]=pack2(a.w);
                        winp[4]=pack2(c.x); winp[5]=pack2(c.y); winp[6]=pack2(c.z); winp[7]=pack2(c.w);
                        winp[8]=pack2(e);
                    }
                    #pragma unroll
                    for (int kx = 0; kx < 6; kx++) {
                        u64 w0 = wp[kx*3 + 0];
                        u64 w1 = wp[kx*3 + 1];
                        u64 w2 = wp[kx*3 + 2];
                        #pragma unroll
                        for (int p = 0; p < 4; p++) {
                            ffma2(acc[p][0], winp[kx+p], w0);
                            ffma2(acc[p][1], winp[kx+p], w1);
                            ffma2(acc[p][2], winp[kx+p], w2);
                        }
                    }
                }
                // --- section 2: kx = 6..10, inputs [6..13] ---
                {
                    u64 winp[8];
                    {
                        float2 a = *(const float2*)(rowp + 6);
                        float4 c = *(const float4*)(rowp + 8);
                        float2 e = *(const float2*)(rowp + 12);
                        winp[0]=pack2(a.x); winp[1]=pack2(a.y);
                        winp[2]=pack2(c.x); winp[3]=pack2(c.y); winp[4]=pack2(c.z); winp[5]=pack2(c.w);
                        winp[6]=pack2(e.x); winp[7]=pack2(e.y);
                    }
                    #pragma unroll
                    for (int kx = 6; kx < 11; kx++) {
                        u64 w0 = wp[kx*3 + 0];
                        u64 w1 = wp[kx*3 + 1];
                        u64 w2 = wp[kx*3 + 2];
                        #pragma unroll
                        for (int p = 0; p < 4; p++) {
                            ffma2(acc[p][0], winp[kx-6+p], w0);
                            ffma2(acc[p][1], winp[kx-6+p], w1);
                            ffma2(acc[p][2], winp[kx-6+p], w2);
                        }
                    }
                }
            }
        }
    }

    // unpack, store z, LN partial sums (this half covers 2 gates)
    const int gy = ty0 + ty;
    const int gx = tx0 + tx4;
    float s[2]  = {0.f, 0.f};
    float ss[2] = {0.f, 0.f};
    #pragma unroll
    for (int j = 0; j < 3; j++) {
        float z0[4], z1[4];
        #pragma unroll
        for (int p = 0; p < 4; p++) unpack2(acc[p][j], z0[p], z1[p]);
        int gl0 = (2*j)   / 3;
        int gl1 = (2*j+1) / 3;
        float4 v0, v1;
        v0.x=z0[0]; v0.y=z0[1]; v0.z=z0[2]; v0.w=z0[3];
        v1.x=z1[0]; v1.y=z1[1]; v1.z=z1[2]; v1.w=z1[3];
        #pragma unroll
        for (int p = 0; p < 4; p++) {
            s[gl0]  += z0[p];  ss[gl0] += z0[p]*z0[p];
            s[gl1]  += z1[p];  ss[gl1] += z1[p]*z1[p];
        }
        *(float4*)&g_z[(size_t)(b*12 + half*6 + 2*j    )*GG + gy*G + gx] = v0;
        *(float4*)&g_z[(size_t)(b*12 + half*6 + 2*j + 1)*GG + gy*G + gx] = v1;
    }

    const int lane = tid & 31;
    const int wrp  = tid >> 5;
    #pragma unroll
    for (int g = 0; g < 2; g++) {
        #pragma unroll
        for (int off = 16; off > 0; off >>= 1) {
            s[g]  += __shfl_down_sync(0xFFFFFFFFu, s[g],  off);
            ss[g] += __shfl_down_sync(0xFFFFFFFFu, ss[g], off);
        }
    }
    if (lane == 0) {
        sred[wrp][0] = s[0];  sred[wrp][1] = ss[0];
        sred[wrp][2] = s[1];  sred[wrp][3] = ss[1];
    }
    __syncthreads();
    if (tid < 4) {
        float v = sred[0][tid] + sred[1][tid] + sred[2][tid] + sred[3][tid];
        g_part[((b*8 + tile)*2 + half)*4 + tid] = v;
    }
}

// ---------------- pointwise gate update: loads issued before stats --------------
__global__ __launch_bounds__(256) void k_gates(const float* __restrict__ wci,
                                               const float* __restrict__ wcf,
                                               const float* __restrict__ wco,
                                               const float* __restrict__ lnw,
                                               const float* __restrict__ lnb)
{
    __shared__ float st[8];
    const int b = blockIdx.x / 12;
    const int r = ((blockIdx.x % 12) * 256 + threadIdx.x) * 4;

    // issue ALL global loads first; their ~600cyc latency overlaps stats + barrier
    const size_t zb = (size_t)b * 12 * GG;
    float4 zi = *(const float4*)&g_z[zb + 0*12288 + r];
    float4 zf = *(const float4*)&g_z[zb + 1*12288 + r];
    float4 zg = *(const float4*)&g_z[zb + 2*12288 + r];
    float4 zo = *(const float4*)&g_z[zb + 3*12288 + r];
    float4 wi = *(const float4*)&lnw[0*12288 + r];
    float4 bi = *(const float4*)&lnb[0*12288 + r];
    float4 wf = *(const float4*)&lnw[1*12288 + r];
    float4 bf = *(const float4*)&lnb[1*12288 + r];
    float4 wg = *(const float4*)&lnw[2*12288 + r];
    float4 bgv= *(const float4*)&lnb[2*12288 + r];
    float4 wo = *(const float4*)&lnw[3*12288 + r];
    float4 bo = *(const float4*)&lnb[3*12288 + r];
    float4 ci = *(const float4*)&wci[r];
    float4 cf = *(const float4*)&wcf[r];
    float4 co = *(const float4*)&wco[r];
    float4 c4 = *(const float4*)&g_c[b*12288 + r];

    if (threadIdx.x < 4) {
        int gt   = threadIdx.x;
        int half = gt >> 1;
        int gl   = gt & 1;
        float s = 0.f, ssum = 0.f;
        #pragma unroll
        for (int tl = 0; tl < 8; tl++) {
            s    += g_part[((b*8 + tl)*2 + half)*4 + gl*2 + 0];
            ssum += g_part[((b*8 + tl)*2 + half)*4 + gl*2 + 1];
        }
        const float inv = 1.f / 12288.f;
        float mu  = s * inv;
        float var = fmaxf(ssum * inv - mu*mu, 0.f);
        st[gt*2 + 0] = mu;
        st[gt*2 + 1] = rsqrtf(var + EPSV);
    }
    __syncthreads();

    float4 cn4, hn4;
    #pragma unroll
    for (int k = 0; k < 4; k++) {
        float vzi = ((const float*)&zi)[k], vzf = ((const float*)&zf)[k];
        float vzg = ((const float*)&zg)[k], vzo = ((const float*)&zo)[k];
        vzi = (vzi - st[0]) * st[1] * ((const float*)&wi)[k] + ((const float*)&bi)[k];
        vzf = (vzf - st[2]) * st[3] * ((const float*)&wf)[k] + ((const float*)&bf)[k];
        vzg = (vzg - st[4]) * st[5] * ((const float*)&wg)[k] + ((const float*)&bgv)[k];
        vzo = (vzo - st[6]) * st[7] * ((const float*)&wo)[k] + ((const float*)&bo)[k];
        float c  = ((const float*)&c4)[k];
        float ig = fsig(vzi + ((const float*)&ci)[k]*c);
        float fg = fsig(vzf + ((const float*)&cf)[k]*c);
        float cn = fg*c + ig*ftanh(vzg);
        float og = fsig(vzo + ((const float*)&co)[k]*cn);
        ((float*)&cn4)[k] = cn;
        ((float*)&hn4)[k] = og * ftanh(cn);
    }
    *(float4*)&g_c[b*12288 + r] = cn4;
    *(float4*)&g_h[b*12288 + r] = hn4;
}

// ---------------- final 37x37 valid conv ----------------
__global__ __launch_bounds__(128) void k_final(const float* __restrict__ cw,
                                               const float* __restrict__ cb,
                                               float* __restrict__ out)
{
    __shared__ float hs[40*64];
    __shared__ float ws[FK*FK];
    const int b   = blockIdx.x / 7;
    const int seg = blockIdx.x % 7;
    const int oy0 = seg * 4;
    const int tid = threadIdx.x;
    const int ly  = tid / 28;
    const int ox  = tid % 28;

    float acc = 0.f;
    for (int hc = 0; hc < HID; hc++) {
        __syncthreads();
        for (int i = tid; i < 40*64; i += 128) {
            int r = i / 64;
            hs[i] = g_h[(size_t)(b*HID + hc)*GG + (oy0 + r)*G + (i - r*64)];
        }
        for (int i = tid; i < FK*FK; i += 128) ws[i] = cw[hc*FK*FK + i];
        __syncthreads();
        if (tid < 112) {
            #pragma unroll 1
            for (int ky = 0; ky < FK; ky++) {
                const float* hr = &hs[(ly + ky)*64 + ox];
                const float* wr = &ws[ky*FK];
                float a = 0.f;
                #pragma unroll
                for (int kx = 0; kx < FK; kx++) a = fmaf(hr[kx], wr[kx], a);
                acc += a;
            }
        }
    }
    if (tid < 112) {
        int oy = oy0 + ly;
        out[b*OUTW*OUTW + oy*OUTW + ox] = acc + cb[0];
    }
}

// ---------------- launch ----------------
extern "C" void kernel_launch(void* const* d_in, const int* in_sizes, int n_in,
                              void* d_out, int out_size)
{
    const float* x   = (const float*)d_in[0];
    const float* Wg  = (const float*)d_in[1];
    const float* bg  = (const float*)d_in[2];
    const float* wci = (const float*)d_in[3];
    const float* wcf = (const float*)d_in[4];
    const float* wco = (const float*)d_in[5];
    const float* lnw = (const float*)d_in[6];
    const float* lnb = (const float*)d_in[7];
    const float* cw  = (const float*)d_in[8];
    const float* cb  = (const float*)d_in[9];
    float* out = (float*)d_out;

    k_init<<<(BB*HID*GG + 255)/256, 256>>>();
    for (int t = 0; t < TT; t++) {
        k_conv<<<BB*16, 128>>>(x, Wg, bg, t);
        k_gates<<<BB*12, 256>>>(wci, wcf, wco, lnw, lnb);
    }
    k_final<<<BB*7, 128>>>(cw, cb, out);
}